// round 13
// baseline (speedup 1.0000x reference)
#include <cuda_runtime.h>
#include <cuda_bf16.h>
#include <cstdint>

#define B_   4
#define T_   1024
#define E_   1024
#define A_   64
#define H_   16
#define AH_  1024
#define M_   4096
#define KDIM 1024

// ---------------------------------------------------------------------------
// Scratch (__device__ globals; no allocations allowed anywhere)
// ---------------------------------------------------------------------------
__device__ __nv_bfloat16 g_qh[M_ * AH_], g_ql[M_ * AH_];
__device__ __nv_bfloat16 g_kh[M_ * AH_], g_kl[M_ * AH_];
__device__ __nv_bfloat16 g_vh[M_ * AH_], g_vl[M_ * AH_];
__device__ __nv_bfloat16 g_zh[M_ * AH_], g_zl[M_ * AH_];
__device__ __nv_bfloat16 g_xh[M_ * E_],  g_xl[M_ * E_];
// weights transposed to [N,K] K-major, split hi/lo. sel: 0=Wq(x0.125) 1=Wk 2=Wv 3=Wo
__device__ __nv_bfloat16 g_wh[4 * KDIM * E_];
__device__ __nv_bfloat16 g_wl[4 * KDIM * E_];

// ---------------------------------------------------------------------------
// PTX helpers (plain sm_80-era features; valid on compute_103 non-'a')
// ---------------------------------------------------------------------------
__device__ __forceinline__ uint32_t smem_to_u32(const void* p) {
    uint32_t a;
    asm("{ .reg .u64 t; cvta.to.shared.u64 t, %1; cvt.u32.u64 %0, t; }"
        : "=r"(a) : "l"(p));
    return a;
}

__device__ __forceinline__ void cp16(uint32_t dst, const void* src) {
    asm volatile("cp.async.cg.shared.global [%0], [%1], 16;"
                 :: "r"(dst), "l"(src) : "memory");
}
#define CP_COMMIT() asm volatile("cp.async.commit_group;" ::: "memory")
#define CP_WAIT(n)  asm volatile("cp.async.wait_group %0;" :: "n"(n) : "memory")

#define LDSM_X4(r0, r1, r2, r3, addr) \
    asm volatile("ldmatrix.sync.aligned.m8n8.x4.shared.b16 {%0,%1,%2,%3}, [%4];" \
                 : "=r"(r0), "=r"(r1), "=r"(r2), "=r"(r3) : "r"(addr))

#define LDSM_X4_T(r0, r1, r2, r3, addr) \
    asm volatile("ldmatrix.sync.aligned.m8n8.x4.trans.shared.b16 {%0,%1,%2,%3}, [%4];" \
                 : "=r"(r0), "=r"(r1), "=r"(r2), "=r"(r3) : "r"(addr))

#define MMA16816(d, a, b) \
    asm volatile("mma.sync.aligned.m16n8k16.row.col.f32.bf16.bf16.f32 " \
                 "{%0,%1,%2,%3}, {%4,%5,%6,%7}, {%8,%9}, {%0,%1,%2,%3};" \
                 : "+f"((d)[0]), "+f"((d)[1]), "+f"((d)[2]), "+f"((d)[3]) \
                 : "r"((a)[0]), "r"((a)[1]), "r"((a)[2]), "r"((a)[3]), \
                   "r"((b)[0]), "r"((b)[1]))

// pack (a -> low half, b -> high half) with hi/lo residual split
__device__ __forceinline__ void split2(float a, float b, uint32_t& h, uint32_t& l) {
    asm("cvt.rn.bf16x2.f32 %0, %1, %2;" : "=r"(h) : "f"(b), "f"(a));
    float ha = __uint_as_float(h << 16);
    float hb = __uint_as_float(h & 0xffff0000u);
    asm("cvt.rn.bf16x2.f32 %0, %1, %2;" : "=r"(l) : "f"(b - hb), "f"(a - ha));
}

// ---------------------------------------------------------------------------
// Fused prep: blocks [0,4096) split x; blocks [4096,8192) transpose+split W.
// ---------------------------------------------------------------------------
__global__ void __launch_bounds__(256) prep_kernel(
    const float* __restrict__ x,
    const float* __restrict__ Wq, const float* __restrict__ Wk,
    const float* __restrict__ Wv, const float* __restrict__ Wo)
{
    const int bid = blockIdx.x;
    const int tid = threadIdx.x;
    if (bid < 4096) {
        int i = bid * 256 + tid;
        float4 v = reinterpret_cast<const float4*>(x)[i];
        uint32_t h0, l0, h1, l1;
        split2(v.x, v.y, h0, l0);
        split2(v.z, v.w, h1, l1);
        uint32_t* xh = reinterpret_cast<uint32_t*>(g_xh) + 2 * i;
        uint32_t* xl = reinterpret_cast<uint32_t*>(g_xl) + 2 * i;
        xh[0] = h0; xh[1] = h1;
        xl[0] = l0; xl[1] = l1;
        return;
    }
    __shared__ float t[32][33];
    const int w = bid - 4096;
    const int sel = w >> 10;                 // 0..3
    const int tile = w & 1023;
    const int bx = tile & 31, by = tile >> 5;
    const float* W = (sel == 0) ? Wq : (sel == 1) ? Wk : (sel == 2) ? Wv : Wo;
    const float wscale = (sel == 0) ? 0.125f : 1.0f;
    const int tx = tid & 31, ty = tid >> 5;  // 32 x 8
    #pragma unroll
    for (int i = 0; i < 4; i++) {
        int r = by * 32 + ty + i * 8;
        t[ty + i * 8][tx] = W[r * 1024 + bx * 32 + tx];
    }
    __syncthreads();
    __nv_bfloat16* wh = g_wh + (size_t)sel * (KDIM * E_);
    __nv_bfloat16* wl = g_wl + (size_t)sel * (KDIM * E_);
    #pragma unroll
    for (int i = 0; i < 4; i++) {
        int n = bx * 32 + ty + i * 8;
        int k = by * 32 + tx;
        float v = t[tx][ty + i * 8] * wscale;
        __nv_bfloat16 h = __float2bfloat16(v);
        wh[n * 1024 + k] = h;
        wl[n * 1024 + k] = __float2bfloat16(v - __bfloat162float(h));
    }
}

// ---------------------------------------------------------------------------
// Warp-MMA bf16-split GEMM (HMMA path). 128x128 tile, 8 warps 2x4, K-chunk 32,
// 3-stage cp.async pipeline, ONE __syncthreads per chunk (prefetch issued
// after the barrier -> WAR-safe), 80B-padded rows (conflict-free ldmatrix).
// ---------------------------------------------------------------------------
#define KC     32
#define NCH    32
#define MATB   10240              // 128 * 40 * 2 bytes
#define STAGEB (4 * MATB)         // AH AL BH BL per stage
#define SOFF(st, m) ((st) * STAGEB + (m) * MATB)
#define GEMM_SMEM (3 * STAGEB)    // 122880 B -> 1 CTA/SM

__device__ __forceinline__ void load_stage(
    uint32_t sb, int st,
    const __nv_bfloat16* __restrict__ Ah, const __nv_bfloat16* __restrict__ Al,
    const __nv_bfloat16* __restrict__ Bh, const __nv_bfloat16* __restrict__ Bl,
    int row0, int col0, int k0)
{
    const int tid = threadIdx.x;
    const __nv_bfloat16* srcs[4] = {Ah, Al, Bh, Bl};
    const int r0s[4] = {row0, row0, col0, col0};
    #pragma unroll
    for (int m = 0; m < 4; m++) {
        const __nv_bfloat16* src = srcs[m];
        const int r0 = r0s[m];
        const uint32_t off = sb + SOFF(st, m);
        #pragma unroll
        for (int j = 0; j < 2; j++) {
            int i = tid + j * 256;
            int row = i >> 2, seg = i & 3;
            cp16(off + row * 80 + seg * 16,
                 src + (size_t)(r0 + row) * 1024 + k0 + seg * 8);
        }
    }
}

template <bool BF16OUT>
__device__ __forceinline__ void gemm_body(
    const __nv_bfloat16* __restrict__ Ah, const __nv_bfloat16* __restrict__ Al,
    const __nv_bfloat16* __restrict__ Bh, const __nv_bfloat16* __restrict__ Bl,
    const float* __restrict__ bias, float bscale,
    float* __restrict__ Cf, __nv_bfloat16* __restrict__ Ch, __nv_bfloat16* __restrict__ Cl,
    int row0, int col0)
{
    extern __shared__ char smem[];
    const uint32_t sb = smem_to_u32(smem);
    const int tid  = threadIdx.x;
    const int wid  = tid >> 5;
    const int lane = tid & 31;
    const int wm = (wid >> 2) * 64;
    const int wn = (wid & 3) * 32;

    const uint32_t aoff = (uint32_t)((lane & 15) * 80 + (lane >> 4) * 16);
    const uint32_t boff = (uint32_t)(((lane & 7) + ((lane >> 4) & 1) * 8) * 80 +
                                     ((lane >> 3) & 1) * 16);

    float acc[4][4][4];
    #pragma unroll
    for (int mf = 0; mf < 4; mf++)
        #pragma unroll
        for (int nf = 0; nf < 4; nf++)
            #pragma unroll
            for (int r = 0; r < 4; r++) acc[mf][nf][r] = 0.0f;

    // prologue: chunks 0 and 1 in flight
    load_stage(sb, 0, Ah, Al, Bh, Bl, row0, col0, 0);
    CP_COMMIT();
    load_stage(sb, 1, Ah, Al, Bh, Bl, row0, col0, KC);
    CP_COMMIT();

    int buf = 0, pre = 2;                    // rotating stage indices
    for (int c = 0; c < NCH; c++) {
        if (c + 1 < NCH) { CP_WAIT(1); } else { CP_WAIT(0); }
        __syncthreads();                     // chunk c visible; stage 'pre' free
        if (c + 2 < NCH) {
            load_stage(sb, pre, Ah, Al, Bh, Bl, row0, col0, (c + 2) * KC);
            CP_COMMIT();
        }

        #pragma unroll
        for (int s = 0; s < 2; s++) {
            const uint32_t ks = (uint32_t)(s * 32);
            uint32_t bh[4][2], bl[4][2];
            #pragma unroll
            for (int pr = 0; pr < 2; pr++) {
                const uint32_t nb0 = (uint32_t)((wn + pr * 16) * 80) + ks + boff;
                LDSM_X4(bh[2 * pr][0], bh[2 * pr][1], bh[2 * pr + 1][0], bh[2 * pr + 1][1],
                        sb + SOFF(buf, 2) + nb0);
                LDSM_X4(bl[2 * pr][0], bl[2 * pr][1], bl[2 * pr + 1][0], bl[2 * pr + 1][1],
                        sb + SOFF(buf, 3) + nb0);
            }
            #pragma unroll
            for (int mf = 0; mf < 4; mf++) {
                const uint32_t ab = (uint32_t)((wm + mf * 16) * 80) + ks + aoff;
                uint32_t ah[4], al[4];
                LDSM_X4(ah[0], ah[1], ah[2], ah[3], sb + SOFF(buf, 0) + ab);
                LDSM_X4(al[0], al[1], al[2], al[3], sb + SOFF(buf, 1) + ab);
                #pragma unroll
                for (int nf = 0; nf < 4; nf++) {
                    MMA16816(acc[mf][nf], ah, bh[nf]);
                    MMA16816(acc[mf][nf], ah, bl[nf]);
                    MMA16816(acc[mf][nf], al, bh[nf]);
                }
            }
        }
        buf = (buf == 2) ? 0 : buf + 1;
        pre = (pre == 2) ? 0 : pre + 1;
    }

    const int g = lane >> 2, tg = lane & 3;
    #pragma unroll
    for (int mf = 0; mf < 4; mf++) {
        const int row = row0 + wm + mf * 16 + g;
        #pragma unroll
        for (int nf = 0; nf < 4; nf++) {
            const int col = col0 + wn + nf * 8 + tg * 2;
            const float2 bv = *reinterpret_cast<const float2*>(bias + col);
            float o00 = acc[mf][nf][0] + bv.x * bscale;
            float o01 = acc[mf][nf][1] + bv.y * bscale;
            float o10 = acc[mf][nf][2] + bv.x * bscale;
            float o11 = acc[mf][nf][3] + bv.y * bscale;
            if (BF16OUT) {
                uint32_t h, l;
                split2(o00, o01, h, l);
                *reinterpret_cast<uint32_t*>(Ch + (size_t)row * 1024 + col) = h;
                *reinterpret_cast<uint32_t*>(Cl + (size_t)row * 1024 + col) = l;
                split2(o10, o11, h, l);
                *reinterpret_cast<uint32_t*>(Ch + (size_t)(row + 8) * 1024 + col) = h;
                *reinterpret_cast<uint32_t*>(Cl + (size_t)(row + 8) * 1024 + col) = l;
            } else {
                float2 o0 = {o00, o01}, o1 = {o10, o11};
                *reinterpret_cast<float2*>(&Cf[(size_t)row * 1024 + col]) = o0;
                *reinterpret_cast<float2*>(&Cf[(size_t)(row + 8) * 1024 + col]) = o1;
            }
        }
    }
}

// grid 768: sel(3) x m(32) x n(8).  Wq pre-scaled by 0.125 -> bias scale 0.125.
__global__ void __launch_bounds__(256, 1) qkv_mma_kernel(
    const float* __restrict__ bq, const float* __restrict__ bk, const float* __restrict__ bv)
{
    const int bx = blockIdx.x;
    const int sel = bx >> 8;
    const int m = (bx >> 3) & 31;
    const int n = bx & 7;
    const __nv_bfloat16* Bh = g_wh + (size_t)sel * (KDIM * E_);
    const __nv_bfloat16* Bl = g_wl + (size_t)sel * (KDIM * E_);
    const float* bias = (sel == 0) ? bq : (sel == 1) ? bk : bv;
    const float bscale = (sel == 0) ? 0.125f : 1.0f;
    __nv_bfloat16* Ch = (sel == 0) ? g_qh : (sel == 1) ? g_kh : g_vh;
    __nv_bfloat16* Cl = (sel == 0) ? g_ql : (sel == 1) ? g_kl : g_vl;
    gemm_body<true>(g_xh, g_xl, Bh, Bl, bias, bscale, nullptr, Ch, Cl, m * 128, n * 128);
}

__global__ void __launch_bounds__(256, 1) out_mma_kernel(
    const float* __restrict__ bo, float* __restrict__ out)
{
    const int bx = blockIdx.x;
    const int m = bx >> 3;
    const int n = bx & 7;
    gemm_body<false>(g_zh, g_zl, g_wh + (size_t)3 * (KDIM * E_), g_wl + (size_t)3 * (KDIM * E_),
                     bo, 1.0f, out, nullptr, nullptr, m * 128, n * 128);
}

// ---------------------------------------------------------------------------
// HMMA flash attention, bf16 hi/lo inputs straight from qkv GEMM.
// CTA = (128-query tile, head-batch). 8 warps x 16 q. Q pre-scaled (in Wq).
// K/V chunks double-buffered via cp.async. Softmax without max-subtraction
// (|s| < ~5). Epilogue writes z/l as bf16 hi/lo (GEMM-ready). 48B rows.
// ---------------------------------------------------------------------------
#define QP 24            // padded row pitch in bf16 elems (48 B)

__device__ __forceinline__ void attn_load_kv(
    uint32_t kh, uint32_t kl, uint32_t vh, uint32_t vl,
    size_t go0 /* gbase + kc*AH_ */, int tid)
{
    const int row = tid >> 2, r = tid & 3, seg = r & 1, kv = r >> 1;
    const uint32_t soff = (uint32_t)(row * 48 + seg * 16);
    const size_t go = go0 + (size_t)row * AH_ + seg * 8;
    if (kv == 0) {
        cp16(kh + soff, g_kh + go);
        cp16(kl + soff, g_kl + go);
    } else {
        cp16(vh + soff, g_vh + go);
        cp16(vl + soff, g_vl + go);
    }
}

__global__ void __launch_bounds__(256) attn_mma_kernel()
{
    __shared__ __nv_bfloat16 Qh[128 * QP], Ql[128 * QP];
    __shared__ __nv_bfloat16 Kh[2][64 * QP], Kl[2][64 * QP];
    __shared__ __nv_bfloat16 Vh[2][64 * QP], Vl[2][64 * QP];

    const int hb = blockIdx.y;              // a*B + b
    const int a = hb >> 2, b = hb & 3;
    const int q0 = blockIdx.x * 128;
    const int tid = threadIdx.x;
    const int wid = tid >> 5, lane = tid & 31;
    const int g = lane >> 2, tg = lane & 3;

    const size_t gbase = (size_t)b * T_ * AH_ + (size_t)a * H_;

    const uint32_t sQh = smem_to_u32(Qh), sQl = smem_to_u32(Ql);
    uint32_t sKh[2] = {smem_to_u32(Kh[0]), smem_to_u32(Kh[1])};
    uint32_t sKl[2] = {smem_to_u32(Kl[0]), smem_to_u32(Kl[1])};
    uint32_t sVh[2] = {smem_to_u32(Vh[0]), smem_to_u32(Vh[1])};
    uint32_t sVl[2] = {smem_to_u32(Vl[0]), smem_to_u32(Vl[1])};

    // group 0: Q tile + K/V chunk 0
    {
        const int row = tid >> 1, seg = tid & 1;
        const uint32_t soff = (uint32_t)(row * 48 + seg * 16);
        const size_t go = gbase + (size_t)(q0 + row) * AH_ + seg * 8;
        cp16(sQh + soff, g_qh + go);
        cp16(sQl + soff, g_ql + go);
    }
    attn_load_kv(sKh[0], sKl[0], sVh[0], sVl[0], gbase, tid);
    CP_COMMIT();

    uint32_t qha[4], qla[4];
    float zacc[2][4];
    #pragma unroll
    for (int nf = 0; nf < 2; nf++)
        #pragma unroll
        for (int r = 0; r < 4; r++) zacc[nf][r] = 0.0f;
    float l0 = 0.0f, l1 = 0.0f;

    const uint32_t qoff = (uint32_t)(
        (wid * 16 + ((lane >> 3) & 1) * 8 + (lane & 7)) * 48 + (lane >> 4) * 16);
    const uint32_t koff = (uint32_t)(
        ((lane >> 4) * 8 + (lane & 7)) * 48 + ((lane >> 3) & 1) * 16);
    const uint32_t voff = (uint32_t)(
        (((lane >> 3) & 1) * 8 + (lane & 7)) * 48 + (lane >> 4) * 16);

    for (int c = 0; c < 16; c++) {
        const int buf = c & 1;
        if (c + 1 < 16) {
            const int nb = buf ^ 1;
            attn_load_kv(sKh[nb], sKl[nb], sVh[nb], sVl[nb],
                         gbase + (size_t)(c + 1) * 64 * AH_, tid);
            CP_COMMIT();
            CP_WAIT(1);
        } else {
            CP_WAIT(0);
        }
        __syncthreads();

        if (c == 0) {
            LDSM_X4(qha[0], qha[1], qha[2], qha[3], sQh + qoff);
            LDSM_X4(qla[0], qla[1], qla[2], qla[3], sQl + qoff);
        }

        // ---- S = Q . K^T  (8 n-frags of 8 keys), 3-term split ----
        float sc[8][4];
        #pragma unroll
        for (int p = 0; p < 4; p++) {
            uint32_t kh[4], kl[4];
            const uint32_t kb = (uint32_t)(p * 16 * 48) + koff;
            LDSM_X4(kh[0], kh[1], kh[2], kh[3], sKh[buf] + kb);
            LDSM_X4(kl[0], kl[1], kl[2], kl[3], sKl[buf] + kb);
            #pragma unroll
            for (int r = 0; r < 4; r++) { sc[2 * p][r] = 0.0f; sc[2 * p + 1][r] = 0.0f; }
            MMA16816(sc[2 * p], qha, kh);
            MMA16816(sc[2 * p], qha, kl);
            MMA16816(sc[2 * p], qla, kh);
            MMA16816(sc[2 * p + 1], qha, kh + 2);
            MMA16816(sc[2 * p + 1], qha, kl + 2);
            MMA16816(sc[2 * p + 1], qla, kh + 2);
        }

        // ---- softmax numerators + pack P as A-fragments (hi/lo) ----
        uint32_t pah[4][4], pal[4][4];
        #pragma unroll
        for (int nf = 0; nf < 8; nf++) {
            float p0 = __expf(sc[nf][0]);
            float p1 = __expf(sc[nf][1]);
            float p2 = __expf(sc[nf][2]);
            float p3 = __expf(sc[nf][3]);
            l0 += p0 + p1;
            l1 += p2 + p3;
            const int s = nf >> 1, o = (nf & 1) * 2;
            split2(p0, p1, pah[s][o + 0], pal[s][o + 0]);
            split2(p2, p3, pah[s][o + 1], pal[s][o + 1]);
        }

        // ---- z += P . V  (4 k-steps of 16 keys, 2 h-frags), 3-term ----
        #pragma unroll
        for (int s = 0; s < 4; s++) {
            uint32_t vh[4], vl[4];
            const uint32_t vb = (uint32_t)(s * 16 * 48) + voff;
            LDSM_X4_T(vh[0], vh[1], vh[2], vh[3], sVh[buf] + vb);
            LDSM_X4_T(vl[0], vl[1], vl[2], vl[3], sVl[buf] + vb);
            MMA16816(zacc[0], pah[s], vh);
            MMA16816(zacc[0], pah[s], vl);
            MMA16816(zacc[0], pal[s], vh);
            MMA16816(zacc[1], pah[s], vh + 2);
            MMA16816(zacc[1], pah[s], vl + 2);
            MMA16816(zacc[1], pal[s], vh + 2);
        }
        __syncthreads();
    }

    l0 += __shfl_xor_sync(0xffffffffu, l0, 1);
    l0 += __shfl_xor_sync(0xffffffffu, l0, 2);
    l1 += __shfl_xor_sync(0xffffffffu, l1, 1);
    l1 += __shfl_xor_sync(0xffffffffu, l1, 2);
    const float inv0 = 1.0f / l0, inv1 = 1.0f / l1;

    const size_t zbase = (size_t)hb * (T_ * H_) + (size_t)(q0 + wid * 16) * H_;
    #pragma unroll
    for (int nf = 0; nf < 2; nf++) {
        const int col = nf * 8 + tg * 2;
        uint32_t h, l;
        size_t o0 = zbase + (size_t)g * H_ + col;
        split2(zacc[nf][0] * inv0, zacc[nf][1] * inv0, h, l);
        *reinterpret_cast<uint32_t*>(g_zh + o0) = h;
        *reinterpret_cast<uint32_t*>(g_zl + o0) = l;
        size_t o1 = zbase + (size_t)(g + 8) * H_ + col;
        split2(zacc[nf][2] * inv1, zacc[nf][3] * inv1, h, l);
        *reinterpret_cast<uint32_t*>(g_zh + o1) = h;
        *reinterpret_cast<uint32_t*>(g_zl + o1) = l;
    }
}

// ---------------------------------------------------------------------------
extern "C" void kernel_launch(void* const* d_in, const int* in_sizes, int n_in,
                              void* d_out, int out_size)
{
    const float* x  = (const float*)d_in[0];
    const float* Wq = (const float*)d_in[1];
    const float* bq = (const float*)d_in[2];
    const float* Wk = (const float*)d_in[3];
    const float* bk = (const float*)d_in[4];
    const float* Wv = (const float*)d_in[5];
    const float* bv = (const float*)d_in[6];
    const float* Wo = (const float*)d_in[7];
    const float* bo = (const float*)d_in[8];
    float* out = (float*)d_out;

    cudaFuncSetAttribute(qkv_mma_kernel, cudaFuncAttributeMaxDynamicSharedMemorySize, GEMM_SMEM);
    cudaFuncSetAttribute(out_mma_kernel, cudaFuncAttributeMaxDynamicSharedMemorySize, GEMM_SMEM);

    prep_kernel<<<8192, 256>>>(x, Wq, Wk, Wv, Wo);
    qkv_mma_kernel<<<768, 256, GEMM_SMEM>>>(bq, bk, bv);
    attn_mma_kernel<<<dim3(T_ / 128, A_ * B_), 256>>>();
    out_mma_kernel<<<256, 256, GEMM_SMEM>>>(bo, out);
}

// round 16
// speedup vs baseline: 1.0827x; 1.0827x over previous
#include <cuda_runtime.h>
#include <cuda_bf16.h>
#include <cstdint>

#define B_   4
#define T_   1024
#define E_   1024
#define A_   64
#define H_   16
#define AH_  1024
#define M_   4096
#define KDIM 1024

// ---------------------------------------------------------------------------
// Scratch (__device__ globals; no allocations allowed anywhere)
// ---------------------------------------------------------------------------
__device__ __nv_bfloat16 g_qh[M_ * AH_], g_ql[M_ * AH_];
__device__ __nv_bfloat16 g_kh[M_ * AH_], g_kl[M_ * AH_];
__device__ __nv_bfloat16 g_vh[M_ * AH_], g_vl[M_ * AH_];
__device__ __nv_bfloat16 g_zh[M_ * AH_], g_zl[M_ * AH_];
__device__ __nv_bfloat16 g_xh[M_ * E_],  g_xl[M_ * E_];
// weights transposed to [N,K] K-major, split hi/lo. sel: 0=Wq(x0.125) 1=Wk 2=Wv 3=Wo
__device__ __nv_bfloat16 g_wh[4 * KDIM * E_];
__device__ __nv_bfloat16 g_wl[4 * KDIM * E_];

// ---------------------------------------------------------------------------
// PTX helpers (plain sm_80-era features; valid on compute_103 non-'a')
// ---------------------------------------------------------------------------
__device__ __forceinline__ uint32_t smem_to_u32(const void* p) {
    uint32_t a;
    asm("{ .reg .u64 t; cvta.to.shared.u64 t, %1; cvt.u32.u64 %0, t; }"
        : "=r"(a) : "l"(p));
    return a;
}

__device__ __forceinline__ void cp16(uint32_t dst, const void* src) {
    asm volatile("cp.async.cg.shared.global [%0], [%1], 16;"
                 :: "r"(dst), "l"(src) : "memory");
}
#define CP_COMMIT() asm volatile("cp.async.commit_group;" ::: "memory")
#define CP_WAIT(n)  asm volatile("cp.async.wait_group %0;" :: "n"(n) : "memory")

#define LDSM_X4(r0, r1, r2, r3, addr) \
    asm volatile("ldmatrix.sync.aligned.m8n8.x4.shared.b16 {%0,%1,%2,%3}, [%4];" \
                 : "=r"(r0), "=r"(r1), "=r"(r2), "=r"(r3) : "r"(addr))

#define LDSM_X4_T(r0, r1, r2, r3, addr) \
    asm volatile("ldmatrix.sync.aligned.m8n8.x4.trans.shared.b16 {%0,%1,%2,%3}, [%4];" \
                 : "=r"(r0), "=r"(r1), "=r"(r2), "=r"(r3) : "r"(addr))

#define MMA16816(d, a, b) \
    asm volatile("mma.sync.aligned.m16n8k16.row.col.f32.bf16.bf16.f32 " \
                 "{%0,%1,%2,%3}, {%4,%5,%6,%7}, {%8,%9}, {%0,%1,%2,%3};" \
                 : "+f"((d)[0]), "+f"((d)[1]), "+f"((d)[2]), "+f"((d)[3]) \
                 : "r"((a)[0]), "r"((a)[1]), "r"((a)[2]), "r"((a)[3]), \
                   "r"((b)[0]), "r"((b)[1]))

// pack (a -> low half, b -> high half) with hi/lo residual split
__device__ __forceinline__ void split2(float a, float b, uint32_t& h, uint32_t& l) {
    asm("cvt.rn.bf16x2.f32 %0, %1, %2;" : "=r"(h) : "f"(b), "f"(a));
    float ha = __uint_as_float(h << 16);
    float hb = __uint_as_float(h & 0xffff0000u);
    asm("cvt.rn.bf16x2.f32 %0, %1, %2;" : "=r"(l) : "f"(b - hb), "f"(a - ha));
}

// ---------------------------------------------------------------------------
// Fused prep: blocks [0,4096) split x; blocks [4096,8192) transpose+split W.
// ---------------------------------------------------------------------------
__global__ void __launch_bounds__(256) prep_kernel(
    const float* __restrict__ x,
    const float* __restrict__ Wq, const float* __restrict__ Wk,
    const float* __restrict__ Wv, const float* __restrict__ Wo)
{
    const int bid = blockIdx.x;
    const int tid = threadIdx.x;
    if (bid < 4096) {
        int i = bid * 256 + tid;
        float4 v = reinterpret_cast<const float4*>(x)[i];
        uint32_t h0, l0, h1, l1;
        split2(v.x, v.y, h0, l0);
        split2(v.z, v.w, h1, l1);
        uint32_t* xh = reinterpret_cast<uint32_t*>(g_xh) + 2 * i;
        uint32_t* xl = reinterpret_cast<uint32_t*>(g_xl) + 2 * i;
        xh[0] = h0; xh[1] = h1;
        xl[0] = l0; xl[1] = l1;
        return;
    }
    __shared__ float t[32][33];
    const int w = bid - 4096;
    const int sel = w >> 10;                 // 0..3
    const int tile = w & 1023;
    const int bx = tile & 31, by = tile >> 5;
    const float* W = (sel == 0) ? Wq : (sel == 1) ? Wk : (sel == 2) ? Wv : Wo;
    const float wscale = (sel == 0) ? 0.125f : 1.0f;
    const int tx = tid & 31, ty = tid >> 5;  // 32 x 8
    #pragma unroll
    for (int i = 0; i < 4; i++) {
        int r = by * 32 + ty + i * 8;
        t[ty + i * 8][tx] = W[r * 1024 + bx * 32 + tx];
    }
    __syncthreads();
    __nv_bfloat16* wh = g_wh + (size_t)sel * (KDIM * E_);
    __nv_bfloat16* wl = g_wl + (size_t)sel * (KDIM * E_);
    #pragma unroll
    for (int i = 0; i < 4; i++) {
        int n = bx * 32 + ty + i * 8;
        int k = by * 32 + tx;
        float v = t[tx][ty + i * 8] * wscale;
        __nv_bfloat16 h = __float2bfloat16(v);
        wh[n * 1024 + k] = h;
        wl[n * 1024 + k] = __float2bfloat16(v - __bfloat162float(h));
    }
}

// ---------------------------------------------------------------------------
// Warp-MMA bf16-split GEMM (HMMA path). 128x128 tile, 8 warps 2x4, K-chunk 32,
// 2-stage cp.async double buffering (80KB smem -> 2 CTA/SM with regs<=128),
// 80B-padded rows (conflict-free ldmatrix).
// R13 ncu showed tensor=44.8% @ occ=12.5% (1 CTA/SM): occupancy is the lever.
// ---------------------------------------------------------------------------
#define KC     32
#define NCH    32
#define MATB   10240              // 128 * 40 * 2 bytes
#define SM_AH(b) ((b) * MATB)
#define SM_AL(b) (2 * MATB + (b) * MATB)
#define SM_BH(b) (4 * MATB + (b) * MATB)
#define SM_BL(b) (6 * MATB + (b) * MATB)
#define GEMM_SMEM (8 * MATB)      // 81920 B -> 2 CTA/SM

__device__ __forceinline__ void load_mat(uint32_t sb, uint32_t off,
                                         const __nv_bfloat16* __restrict__ src,
                                         int r0, int k0) {
    const int tid = threadIdx.x;
    #pragma unroll
    for (int j = 0; j < 2; j++) {
        int i = tid + j * 256;
        int row = i >> 2, seg = i & 3;
        cp16(sb + off + row * 80 + seg * 16,
             src + (size_t)(r0 + row) * 1024 + k0 + seg * 8);
    }
}

template <bool BF16OUT>
__device__ __forceinline__ void gemm_body(
    const __nv_bfloat16* __restrict__ Ah, const __nv_bfloat16* __restrict__ Al,
    const __nv_bfloat16* __restrict__ Bh, const __nv_bfloat16* __restrict__ Bl,
    const float* __restrict__ bias, float bscale,
    float* __restrict__ Cf, __nv_bfloat16* __restrict__ Ch, __nv_bfloat16* __restrict__ Cl,
    int row0, int col0)
{
    extern __shared__ char smem[];
    const uint32_t sb = smem_to_u32(smem);
    const int tid  = threadIdx.x;
    const int wid  = tid >> 5;
    const int lane = tid & 31;
    const int wm = (wid >> 2) * 64;
    const int wn = (wid & 3) * 32;

    const uint32_t aoff = (uint32_t)((lane & 15) * 80 + (lane >> 4) * 16);
    const uint32_t boff = (uint32_t)(((lane & 7) + ((lane >> 4) & 1) * 8) * 80 +
                                     ((lane >> 3) & 1) * 16);

    float acc[4][4][4];
    #pragma unroll
    for (int mf = 0; mf < 4; mf++)
        #pragma unroll
        for (int nf = 0; nf < 4; nf++)
            #pragma unroll
            for (int r = 0; r < 4; r++) acc[mf][nf][r] = 0.0f;

    load_mat(sb, SM_AH(0), Ah, row0, 0);
    load_mat(sb, SM_AL(0), Al, row0, 0);
    load_mat(sb, SM_BH(0), Bh, col0, 0);
    load_mat(sb, SM_BL(0), Bl, col0, 0);
    CP_COMMIT();

    for (int c = 0; c < NCH; c++) {
        const int buf = c & 1;
        if (c + 1 < NCH) {
            const int nb = (c + 1) & 1, k0 = (c + 1) * KC;
            load_mat(sb, SM_AH(nb), Ah, row0, k0);
            load_mat(sb, SM_AL(nb), Al, row0, k0);
            load_mat(sb, SM_BH(nb), Bh, col0, k0);
            load_mat(sb, SM_BL(nb), Bl, col0, k0);
            CP_COMMIT();
            CP_WAIT(1);
        } else {
            CP_WAIT(0);
        }
        __syncthreads();

        #pragma unroll
        for (int s = 0; s < 2; s++) {
            const uint32_t ks = (uint32_t)(s * 32);
            uint32_t bh[4][2], bl[4][2];
            #pragma unroll
            for (int pr = 0; pr < 2; pr++) {
                const uint32_t nb0 = (uint32_t)((wn + pr * 16) * 80) + ks + boff;
                LDSM_X4(bh[2 * pr][0], bh[2 * pr][1], bh[2 * pr + 1][0], bh[2 * pr + 1][1],
                        sb + SM_BH(buf) + nb0);
                LDSM_X4(bl[2 * pr][0], bl[2 * pr][1], bl[2 * pr + 1][0], bl[2 * pr + 1][1],
                        sb + SM_BL(buf) + nb0);
            }
            #pragma unroll
            for (int mf = 0; mf < 4; mf++) {
                const uint32_t ab = (uint32_t)((wm + mf * 16) * 80) + ks + aoff;
                uint32_t ah[4], al[4];
                LDSM_X4(ah[0], ah[1], ah[2], ah[3], sb + SM_AH(buf) + ab);
                LDSM_X4(al[0], al[1], al[2], al[3], sb + SM_AL(buf) + ab);
                #pragma unroll
                for (int nf = 0; nf < 4; nf++) {
                    MMA16816(acc[mf][nf], ah, bh[nf]);
                    MMA16816(acc[mf][nf], ah, bl[nf]);
                    MMA16816(acc[mf][nf], al, bh[nf]);
                }
            }
        }
        __syncthreads();
    }

    const int g = lane >> 2, tg = lane & 3;
    #pragma unroll
    for (int mf = 0; mf < 4; mf++) {
        const int row = row0 + wm + mf * 16 + g;
        #pragma unroll
        for (int nf = 0; nf < 4; nf++) {
            const int col = col0 + wn + nf * 8 + tg * 2;
            const float2 bv = *reinterpret_cast<const float2*>(bias + col);
            float o00 = acc[mf][nf][0] + bv.x * bscale;
            float o01 = acc[mf][nf][1] + bv.y * bscale;
            float o10 = acc[mf][nf][2] + bv.x * bscale;
            float o11 = acc[mf][nf][3] + bv.y * bscale;
            if (BF16OUT) {
                uint32_t h, l;
                split2(o00, o01, h, l);
                *reinterpret_cast<uint32_t*>(Ch + (size_t)row * 1024 + col) = h;
                *reinterpret_cast<uint32_t*>(Cl + (size_t)row * 1024 + col) = l;
                split2(o10, o11, h, l);
                *reinterpret_cast<uint32_t*>(Ch + (size_t)(row + 8) * 1024 + col) = h;
                *reinterpret_cast<uint32_t*>(Cl + (size_t)(row + 8) * 1024 + col) = l;
            } else {
                float2 o0 = {o00, o01}, o1 = {o10, o11};
                *reinterpret_cast<float2*>(&Cf[(size_t)row * 1024 + col]) = o0;
                *reinterpret_cast<float2*>(&Cf[(size_t)(row + 8) * 1024 + col]) = o1;
            }
        }
    }
}

// grid 768: sel(3) x m(32) x n(8).  Wq pre-scaled by 0.125 -> bias scale 0.125.
__global__ void __launch_bounds__(256, 2) qkv_mma_kernel(
    const float* __restrict__ bq, const float* __restrict__ bk, const float* __restrict__ bv)
{
    const int bx = blockIdx.x;
    const int sel = bx >> 8;
    const int m = (bx >> 3) & 31;
    const int n = bx & 7;
    const __nv_bfloat16* Bh = g_wh + (size_t)sel * (KDIM * E_);
    const __nv_bfloat16* Bl = g_wl + (size_t)sel * (KDIM * E_);
    const float* bias = (sel == 0) ? bq : (sel == 1) ? bk : bv;
    const float bscale = (sel == 0) ? 0.125f : 1.0f;
    __nv_bfloat16* Ch = (sel == 0) ? g_qh : (sel == 1) ? g_kh : g_vh;
    __nv_bfloat16* Cl = (sel == 0) ? g_ql : (sel == 1) ? g_kl : g_vl;
    gemm_body<true>(g_xh, g_xl, Bh, Bl, bias, bscale, nullptr, Ch, Cl, m * 128, n * 128);
}

__global__ void __launch_bounds__(256, 2) out_mma_kernel(
    const float* __restrict__ bo, float* __restrict__ out)
{
    const int bx = blockIdx.x;
    const int m = bx >> 3;
    const int n = bx & 7;
    gemm_body<false>(g_zh, g_zl, g_wh + (size_t)3 * (KDIM * E_), g_wl + (size_t)3 * (KDIM * E_),
                     bo, 1.0f, out, nullptr, nullptr, m * 128, n * 128);
}

// ---------------------------------------------------------------------------
// HMMA flash attention, bf16 hi/lo inputs straight from qkv GEMM.
// CTA = (128-query tile, head-batch). 8 warps x 16 q. Q pre-scaled (in Wq).
// K/V chunks double-buffered via cp.async. Softmax without max-subtraction
// (|s| < ~5). Epilogue writes z/l as bf16 hi/lo (GEMM-ready). 48B rows.
// ---------------------------------------------------------------------------
#define QP 24            // padded row pitch in bf16 elems (48 B)

__device__ __forceinline__ void attn_load_kv(
    uint32_t kh, uint32_t kl, uint32_t vh, uint32_t vl,
    size_t go0 /* gbase + kc*AH_ */, int tid)
{
    const int row = tid >> 2, r = tid & 3, seg = r & 1, kv = r >> 1;
    const uint32_t soff = (uint32_t)(row * 48 + seg * 16);
    const size_t go = go0 + (size_t)row * AH_ + seg * 8;
    if (kv == 0) {
        cp16(kh + soff, g_kh + go);
        cp16(kl + soff, g_kl + go);
    } else {
        cp16(vh + soff, g_vh + go);
        cp16(vl + soff, g_vl + go);
    }
}

__global__ void __launch_bounds__(256) attn_mma_kernel()
{
    __shared__ __nv_bfloat16 Qh[128 * QP], Ql[128 * QP];
    __shared__ __nv_bfloat16 Kh[2][64 * QP], Kl[2][64 * QP];
    __shared__ __nv_bfloat16 Vh[2][64 * QP], Vl[2][64 * QP];

    const int hb = blockIdx.y;              // a*B + b
    const int a = hb >> 2, b = hb & 3;
    const int q0 = blockIdx.x * 128;
    const int tid = threadIdx.x;
    const int wid = tid >> 5, lane = tid & 31;
    const int g = lane >> 2, tg = lane & 3;

    const size_t gbase = (size_t)b * T_ * AH_ + (size_t)a * H_;

    const uint32_t sQh = smem_to_u32(Qh), sQl = smem_to_u32(Ql);
    uint32_t sKh[2] = {smem_to_u32(Kh[0]), smem_to_u32(Kh[1])};
    uint32_t sKl[2] = {smem_to_u32(Kl[0]), smem_to_u32(Kl[1])};
    uint32_t sVh[2] = {smem_to_u32(Vh[0]), smem_to_u32(Vh[1])};
    uint32_t sVl[2] = {smem_to_u32(Vl[0]), smem_to_u32(Vl[1])};

    // group 0: Q tile + K/V chunk 0
    {
        const int row = tid >> 1, seg = tid & 1;
        const uint32_t soff = (uint32_t)(row * 48 + seg * 16);
        const size_t go = gbase + (size_t)(q0 + row) * AH_ + seg * 8;
        cp16(sQh + soff, g_qh + go);
        cp16(sQl + soff, g_ql + go);
    }
    attn_load_kv(sKh[0], sKl[0], sVh[0], sVl[0], gbase, tid);
    CP_COMMIT();

    uint32_t qha[4], qla[4];
    float zacc[2][4];
    #pragma unroll
    for (int nf = 0; nf < 2; nf++)
        #pragma unroll
        for (int r = 0; r < 4; r++) zacc[nf][r] = 0.0f;
    float l0 = 0.0f, l1 = 0.0f;

    const uint32_t qoff = (uint32_t)(
        (wid * 16 + ((lane >> 3) & 1) * 8 + (lane & 7)) * 48 + (lane >> 4) * 16);
    const uint32_t koff = (uint32_t)(
        ((lane >> 4) * 8 + (lane & 7)) * 48 + ((lane >> 3) & 1) * 16);
    const uint32_t voff = (uint32_t)(
        (((lane >> 3) & 1) * 8 + (lane & 7)) * 48 + (lane >> 4) * 16);

    for (int c = 0; c < 16; c++) {
        const int buf = c & 1;
        if (c + 1 < 16) {
            const int nb = buf ^ 1;
            attn_load_kv(sKh[nb], sKl[nb], sVh[nb], sVl[nb],
                         gbase + (size_t)(c + 1) * 64 * AH_, tid);
            CP_COMMIT();
            CP_WAIT(1);
        } else {
            CP_WAIT(0);
        }
        __syncthreads();

        if (c == 0) {
            LDSM_X4(qha[0], qha[1], qha[2], qha[3], sQh + qoff);
            LDSM_X4(qla[0], qla[1], qla[2], qla[3], sQl + qoff);
        }

        // ---- S = Q . K^T  (8 n-frags of 8 keys), 3-term split ----
        float sc[8][4];
        #pragma unroll
        for (int p = 0; p < 4; p++) {
            uint32_t kh[4], kl[4];
            const uint32_t kb = (uint32_t)(p * 16 * 48) + koff;
            LDSM_X4(kh[0], kh[1], kh[2], kh[3], sKh[buf] + kb);
            LDSM_X4(kl[0], kl[1], kl[2], kl[3], sKl[buf] + kb);
            #pragma unroll
            for (int r = 0; r < 4; r++) { sc[2 * p][r] = 0.0f; sc[2 * p + 1][r] = 0.0f; }
            MMA16816(sc[2 * p], qha, kh);
            MMA16816(sc[2 * p], qha, kl);
            MMA16816(sc[2 * p], qla, kh);
            MMA16816(sc[2 * p + 1], qha, kh + 2);
            MMA16816(sc[2 * p + 1], qha, kl + 2);
            MMA16816(sc[2 * p + 1], qla, kh + 2);
        }

        // ---- softmax numerators + pack P as A-fragments (hi/lo) ----
        uint32_t pah[4][4], pal[4][4];
        #pragma unroll
        for (int nf = 0; nf < 8; nf++) {
            float p0 = __expf(sc[nf][0]);
            float p1 = __expf(sc[nf][1]);
            float p2 = __expf(sc[nf][2]);
            float p3 = __expf(sc[nf][3]);
            l0 += p0 + p1;
            l1 += p2 + p3;
            const int s = nf >> 1, o = (nf & 1) * 2;
            split2(p0, p1, pah[s][o + 0], pal[s][o + 0]);
            split2(p2, p3, pah[s][o + 1], pal[s][o + 1]);
        }

        // ---- z += P . V  (4 k-steps of 16 keys, 2 h-frags), 3-term ----
        #pragma unroll
        for (int s = 0; s < 4; s++) {
            uint32_t vh[4], vl[4];
            const uint32_t vb = (uint32_t)(s * 16 * 48) + voff;
            LDSM_X4_T(vh[0], vh[1], vh[2], vh[3], sVh[buf] + vb);
            LDSM_X4_T(vl[0], vl[1], vl[2], vl[3], sVl[buf] + vb);
            MMA16816(zacc[0], pah[s], vh);
            MMA16816(zacc[0], pah[s], vl);
            MMA16816(zacc[0], pal[s], vh);
            MMA16816(zacc[1], pah[s], vh + 2);
            MMA16816(zacc[1], pah[s], vl + 2);
            MMA16816(zacc[1], pal[s], vh + 2);
        }
        __syncthreads();
    }

    l0 += __shfl_xor_sync(0xffffffffu, l0, 1);
    l0 += __shfl_xor_sync(0xffffffffu, l0, 2);
    l1 += __shfl_xor_sync(0xffffffffu, l1, 1);
    l1 += __shfl_xor_sync(0xffffffffu, l1, 2);
    const float inv0 = 1.0f / l0, inv1 = 1.0f / l1;

    const size_t zbase = (size_t)hb * (T_ * H_) + (size_t)(q0 + wid * 16) * H_;
    #pragma unroll
    for (int nf = 0; nf < 2; nf++) {
        const int col = nf * 8 + tg * 2;
        uint32_t h, l;
        size_t o0 = zbase + (size_t)g * H_ + col;
        split2(zacc[nf][0] * inv0, zacc[nf][1] * inv0, h, l);
        *reinterpret_cast<uint32_t*>(g_zh + o0) = h;
        *reinterpret_cast<uint32_t*>(g_zl + o0) = l;
        size_t o1 = zbase + (size_t)(g + 8) * H_ + col;
        split2(zacc[nf][2] * inv1, zacc[nf][3] * inv1, h, l);
        *reinterpret_cast<uint32_t*>(g_zh + o1) = h;
        *reinterpret_cast<uint32_t*>(g_zl + o1) = l;
    }
}

// ---------------------------------------------------------------------------
extern "C" void kernel_launch(void* const* d_in, const int* in_sizes, int n_in,
                              void* d_out, int out_size)
{
    const float* x  = (const float*)d_in[0];
    const float* Wq = (const float*)d_in[1];
    const float* bq = (const float*)d_in[2];
    const float* Wk = (const float*)d_in[3];
    const float* bk = (const float*)d_in[4];
    const float* Wv = (const float*)d_in[5];
    const float* bv = (const float*)d_in[6];
    const float* Wo = (const float*)d_in[7];
    const float* bo = (const float*)d_in[8];
    float* out = (float*)d_out;

    cudaFuncSetAttribute(qkv_mma_kernel, cudaFuncAttributeMaxDynamicSharedMemorySize, GEMM_SMEM);
    cudaFuncSetAttribute(out_mma_kernel, cudaFuncAttributeMaxDynamicSharedMemorySize, GEMM_SMEM);

    prep_kernel<<<8192, 256>>>(x, Wq, Wk, Wv, Wo);
    qkv_mma_kernel<<<768, 256, GEMM_SMEM>>>(bq, bk, bv);
    attn_mma_kernel<<<dim3(T_ / 128, A_ * B_), 256>>>();
    out_mma_kernel<<<256, 256, GEMM_SMEM>>>(bo, out);
}